// round 1
// baseline (speedup 1.0000x reference)
#include <cuda_runtime.h>

#define NP 50000          // N_PROT
#define ND 5000           // N_DRUG
#define EPP 1600000
#define EPD 200000
#define INP 128           // IN_PROT / IN_DRUG
#define D1 64
#define D2 32
#define OUTD 64

// ---------------- scratch (device globals: no allocation allowed) ----------------
__device__ int   g_deg[NP];
__device__ float g_dinv[NP];
__device__ float g_h1[NP * D1];    // x_prot @ W1
__device__ float g_o1[NP * D1];    // after propagate (pre-relu)
__device__ float g_h2[NP * D2];    // relu(o1) @ W2
__device__ float g_agg[ND * D2];
__device__ float g_cnt[ND];

// ---------------- init / degree ----------------
__global__ void k_zero() {
    int gid = blockIdx.x * blockDim.x + threadIdx.x;
    int stride = gridDim.x * blockDim.x;
    for (int i = gid; i < NP; i += stride) g_deg[i] = 0;
    for (int i = gid; i < ND * D2; i += stride) g_agg[i] = 0.f;
    for (int i = gid; i < ND; i += stride) g_cnt[i] = 0.f;
}

__global__ void k_degree(const int* __restrict__ dst) {
    int e = blockIdx.x * blockDim.x + threadIdx.x;
    if (e < EPP) atomicAdd(&g_deg[dst[e]], 1);
}

__global__ void k_dinv() {
    int i = blockIdx.x * blockDim.x + threadIdx.x;
    if (i < NP) g_dinv[i] = rsqrtf((float)g_deg[i] + 1.0f);  // +1 = self loop
}

// ---------------- GEMM: Y[N,M] = (RELU? relu(X):X)[N,K] @ W[K,M] ----------------
template <int K, int M, bool RELU>
__global__ void k_gemm(const float* __restrict__ X, const float* __restrict__ W,
                       float* __restrict__ Y, int N) {
    constexpr int RG  = 256 / M;   // row groups per block
    constexpr int RPT = 4;         // rows per thread
    constexpr int RPB = RG * RPT;  // rows per block
    __shared__ float Ws[K * M];
    __shared__ float Xs[RPB * K];
    const int tid = threadIdx.x;
    for (int i = tid; i < K * M; i += 256) Ws[i] = W[i];
    const int row0 = blockIdx.x * RPB;
    for (int i = tid; i < RPB * K; i += 256) {
        int r = i / K, k = i - r * K;
        int gr = row0 + r;
        float v = (gr < N) ? X[(long long)gr * K + k] : 0.f;
        if (RELU) v = fmaxf(v, 0.f);
        Xs[i] = v;
    }
    __syncthreads();
    const int c  = tid % M;
    const int rg = tid / M;
    float acc[RPT] = {0.f, 0.f, 0.f, 0.f};
#pragma unroll 4
    for (int k = 0; k < K; k++) {
        float w = Ws[k * M + c];
#pragma unroll
        for (int j = 0; j < RPT; j++)
            acc[j] = fmaf(Xs[(rg * RPT + j) * K + k], w, acc[j]);
    }
#pragma unroll
    for (int j = 0; j < RPT; j++) {
        int r = row0 + rg * RPT + j;
        if (r < N) Y[(long long)r * M + c] = acc[j];
    }
}

// ---------------- self-loop + bias init: out[i,c] = b[c] + dinv[i]^2 * hlin[i,c] ----------------
template <int M>
__global__ void k_init_out(const float* __restrict__ hlin, const float* __restrict__ b,
                           float* __restrict__ out) {
    int gid = blockIdx.x * blockDim.x + threadIdx.x;
    if (gid >= NP * M) return;
    int i = gid / M, c = gid - i * M;
    float di = g_dinv[i];
    out[gid] = b[c] + di * di * hlin[gid];
}

// ---------------- edge scatter: out[dst] += dinv[src]*dinv[dst] * hin[src] ----------------
template <int M>
__global__ void k_scatter(const int* __restrict__ src, const int* __restrict__ dst,
                          const float* __restrict__ hin, float* __restrict__ hout) {
    long long gid = (long long)blockIdx.x * blockDim.x + threadIdx.x;
    int e = (int)(gid / M);
    int c = (int)(gid - (long long)e * M);
    if (e >= EPP) return;
    int s = src[e], d = dst[e];
    float w = g_dinv[s] * g_dinv[d];
    atomicAdd(&hout[d * M + c], w * hin[s * M + c]);
}

// ---------------- drug aggregation ----------------
__global__ void k_drug_cnt(const int* __restrict__ pdd) {
    int e = blockIdx.x * blockDim.x + threadIdx.x;
    if (e < EPD) atomicAdd(&g_cnt[pdd[e]], 1.0f);
}

__global__ void k_drug_agg(const int* __restrict__ pds, const int* __restrict__ pdd,
                           const float* __restrict__ h) {
    int gid = blockIdx.x * blockDim.x + threadIdx.x;
    int e = gid / D2;
    int c = gid - e * D2;
    if (e >= EPD) return;
    atomicAdd(&g_agg[pdd[e] * D2 + c], h[pds[e] * D2 + c]);
}

// ---------------- final drug GEMM: out = mean @ Wl + bl + x_drug @ Wr ----------------
__global__ void k_drug_out(const float* __restrict__ xd, const float* __restrict__ Wl,
                           const float* __restrict__ bl, const float* __restrict__ Wr,
                           float* __restrict__ out) {
    __shared__ float Wls[D2 * OUTD];    // 2048
    __shared__ float Wrs[INP * OUTD];   // 8192
    __shared__ float bls[OUTD];
    __shared__ float Ms[4 * D2];
    __shared__ float Xs[4 * INP];
    const int tid = threadIdx.x;
    for (int i = tid; i < D2 * OUTD; i += 256) Wls[i] = Wl[i];
    for (int i = tid; i < INP * OUTD; i += 256) Wrs[i] = Wr[i];
    if (tid < OUTD) bls[tid] = bl[tid];
    const int row0 = blockIdx.x * 4;  // 5000 % 4 == 0
    for (int i = tid; i < 4 * D2; i += 256) {
        int r = row0 + i / D2;
        float cnt = fmaxf(g_cnt[r], 1.0f);
        Ms[i] = g_agg[r * D2 + (i % D2)] / cnt;
    }
    for (int i = tid; i < 4 * INP; i += 256)
        Xs[i] = xd[(row0 + i / INP) * INP + (i % INP)];
    __syncthreads();
    const int c = tid % OUTD;
    const int r = tid / OUTD;
    float acc = bls[c];
#pragma unroll
    for (int k = 0; k < D2; k++) acc = fmaf(Ms[r * D2 + k], Wls[k * OUTD + c], acc);
#pragma unroll 8
    for (int k = 0; k < INP; k++) acc = fmaf(Xs[r * INP + k], Wrs[k * OUTD + c], acc);
    out[(row0 + r) * OUTD + c] = acc;
}

// ---------------- host ----------------
extern "C" void kernel_launch(void* const* d_in, const int* in_sizes, int n_in,
                              void* d_out, int out_size) {
    const float *x_prot = 0, *x_drug = 0, *W1 = 0, *b1 = 0, *W2 = 0, *b2 = 0;
    const float *Wl = 0, *bl = 0, *Wr = 0;
    const int *pp = 0, *pds = 0, *pdd = 0;
    int n200k = 0, n8192 = 0, n64 = 0, n2048 = 0;
    for (int i = 0; i < n_in; i++) {
        int s = in_sizes[i];
        void* p = d_in[i];
        if (s == NP * INP)        x_prot = (const float*)p;
        else if (s == ND * INP)   x_drug = (const float*)p;
        else if (s == 2 * EPP)    pp = (const int*)p;
        else if (s == EPD) {      if (n200k++ == 0) pds = (const int*)p; else pdd = (const int*)p; }
        else if (s == INP * D1) { if (n8192++ == 0) W1 = (const float*)p; else Wr = (const float*)p; }
        else if (s == D1) {       if (n64++   == 0) b1 = (const float*)p; else bl = (const float*)p; }
        else if (s == D1 * D2) {  if (n2048++ == 0) W2 = (const float*)p; else Wl = (const float*)p; }
        else if (s == D2)         b2 = (const float*)p;
    }
    const int* pp_src = pp;
    const int* pp_dst = pp + EPP;
    float* h_out = (float*)d_out;              // [NP, D2]
    float* drug_out = h_out + (long long)NP * D2;  // [ND, OUTD]

    float* g_h1_p; cudaGetSymbolAddress((void**)&g_h1_p, g_h1);
    float* g_o1_p; cudaGetSymbolAddress((void**)&g_o1_p, g_o1);
    float* g_h2_p; cudaGetSymbolAddress((void**)&g_h2_p, g_h2);

    // degrees + dinv
    k_zero<<<256, 256>>>();
    k_degree<<<(EPP + 255) / 256, 256>>>(pp_dst);
    k_dinv<<<(NP + 255) / 256, 256>>>();

    // layer 1: gemm -> init(self loop + bias) -> scatter
    k_gemm<INP, D1, false><<<(NP + 15) / 16, 256>>>(x_prot, W1, g_h1_p, NP);
    k_init_out<D1><<<(NP * D1 + 255) / 256, 256>>>(g_h1_p, b1, g_o1_p);
    k_scatter<D1><<<(int)(((long long)EPP * D1 + 255) / 256), 256>>>(pp_src, pp_dst, g_h1_p, g_o1_p);

    // layer 2: relu fused into gemm load
    k_gemm<D1, D2, true><<<(NP + 31) / 32, 256>>>(g_o1_p, W2, g_h2_p, NP);
    k_init_out<D2><<<(NP * D2 + 255) / 256, 256>>>(g_h2_p, b2, h_out);
    k_scatter<D2><<<(int)(((long long)EPP * D2 + 255) / 256), 256>>>(pp_src, pp_dst, g_h2_p, h_out);

    // bipartite mean-SAGE
    k_drug_cnt<<<(EPD + 255) / 256, 256>>>(pdd);
    k_drug_agg<<<(EPD * D2 + 255) / 256, 256>>>(pds, pdd, h_out);
    k_drug_out<<<ND / 4, 256>>>(x_drug, Wl, bl, Wr, drug_out);

    (void)out_size;
}

// round 2
// speedup vs baseline: 2.3324x; 2.3324x over previous
#include <cuda_runtime.h>

#define NP 50000          // N_PROT
#define ND 5000           // N_DRUG
#define EPP 1600000
#define EPD 200000
#define INP 128           // IN_PROT / IN_DRUG
#define D1 64
#define D2 32
#define OUTD 64

// ---------------- scratch (device globals: no allocation allowed) ----------------
__device__ int   g_deg[NP];
__device__ float g_dinv[NP];
__device__ float g_w[EPP];         // per-edge weight dinv[s]*dinv[d]
__device__ float g_h1[NP * D1];    // x_prot @ W1 (raw)
__device__ float g_o1[NP * D1];    // b1 + dinv^2*h1, then += edge scatter
__device__ float g_h2[NP * D2];    // relu(o1) @ W2 (raw)
__device__ float g_agg[ND * D2];
__device__ float g_cnt[ND];

// ---------------- vector reduction helper (sm_90+) ----------------
__device__ __forceinline__ void red_add_v4(float* p, float x, float y, float z, float w) {
    asm volatile("red.global.add.v4.f32 [%0], {%1,%2,%3,%4};"
                 :: "l"(p), "f"(x), "f"(y), "f"(z), "f"(w) : "memory");
}

// ---------------- init / degree ----------------
__global__ void k_zero() {
    int gid = blockIdx.x * blockDim.x + threadIdx.x;
    int stride = gridDim.x * blockDim.x;
    for (int i = gid; i < NP; i += stride) g_deg[i] = 0;
    for (int i = gid; i < ND * D2; i += stride) g_agg[i] = 0.f;
    for (int i = gid; i < ND; i += stride) g_cnt[i] = 0.f;
}

__global__ void k_degree(const int* __restrict__ dst) {
    int e = blockIdx.x * blockDim.x + threadIdx.x;
    if (e < EPP) atomicAdd(&g_deg[dst[e]], 1);
}

__global__ void k_dinv() {
    int i = blockIdx.x * blockDim.x + threadIdx.x;
    if (i < NP) g_dinv[i] = rsqrtf((float)g_deg[i] + 1.0f);  // +1 = self loop
}

__global__ void k_edgew(const int* __restrict__ src, const int* __restrict__ dst) {
    int e = blockIdx.x * blockDim.x + threadIdx.x;
    if (e < EPP) g_w[e] = g_dinv[src[e]] * g_dinv[dst[e]];
}

// ---------------- GEMM with fused epilogue ----------------
// Yraw = (RELU? relu(X) : X) @ W           [N, M]
// Oini = bias + dinv^2 * Yraw              [N, M]
// Register tiling: each thread computes 4 rows x 4 cols.
template <int K, int M, int KC, bool RELU>
__global__ void __launch_bounds__(256)
k_gemm(const float* __restrict__ X, const float* __restrict__ W,
       const float* __restrict__ bias, float* __restrict__ Yraw,
       float* __restrict__ Oini, int N) {
    constexpr int CG  = M / 4;          // col groups (16 or 8)
    constexpr int RG  = 256 / CG;       // row groups (16 or 32)
    constexpr int RPB = RG * 4;         // rows per block (64 or 128)
    constexpr int KCP = KC + 2;         // padded chunk row (bank spread = 8/rg-step)
    __shared__ float Ws[K * M];
    __shared__ float Xs[RPB][KCP];

    const int tid = threadIdx.x;
    for (int i = tid; i < K * M; i += 256) Ws[i] = W[i];

    const int row0 = blockIdx.x * RPB;
    const int cg = tid % CG, rg = tid / CG;
    const int c0 = cg * 4, r0 = rg * 4;
    float acc[4][4];
#pragma unroll
    for (int j = 0; j < 4; j++)
#pragma unroll
        for (int i = 0; i < 4; i++) acc[j][i] = 0.f;

    for (int kc0 = 0; kc0 < K; kc0 += KC) {
        // load chunk: RPB rows x KC cols
        constexpr int NV = RPB * KC / 4;       // float4 count
#pragma unroll
        for (int v = 0; v < NV / 256; v++) {
            int idx = tid + v * 256;
            int r = idx / (KC / 4), kq = idx % (KC / 4);
            int gr = row0 + r;
            float4 x = make_float4(0.f, 0.f, 0.f, 0.f);
            if (gr < N) x = *(const float4*)&X[(long long)gr * K + kc0 + kq * 4];
            if (RELU) {
                x.x = fmaxf(x.x, 0.f); x.y = fmaxf(x.y, 0.f);
                x.z = fmaxf(x.z, 0.f); x.w = fmaxf(x.w, 0.f);
            }
            Xs[r][kq * 4 + 0] = x.x; Xs[r][kq * 4 + 1] = x.y;
            Xs[r][kq * 4 + 2] = x.z; Xs[r][kq * 4 + 3] = x.w;
        }
        __syncthreads();
#pragma unroll 4
        for (int k = 0; k < KC; k++) {
            float4 wb = *(const float4*)&Ws[(kc0 + k) * M + c0];
#pragma unroll
            for (int j = 0; j < 4; j++) {
                float xa = Xs[r0 + j][k];
                acc[j][0] = fmaf(xa, wb.x, acc[j][0]);
                acc[j][1] = fmaf(xa, wb.y, acc[j][1]);
                acc[j][2] = fmaf(xa, wb.z, acc[j][2]);
                acc[j][3] = fmaf(xa, wb.w, acc[j][3]);
            }
        }
        __syncthreads();
    }

    const float4 bv = *(const float4*)&bias[c0];
#pragma unroll
    for (int j = 0; j < 4; j++) {
        int gr = row0 + r0 + j;
        if (gr < N) {
            float4 y = make_float4(acc[j][0], acc[j][1], acc[j][2], acc[j][3]);
            *(float4*)&Yraw[(long long)gr * M + c0] = y;
            float di = g_dinv[gr];
            float d2 = di * di;
            float4 o = make_float4(fmaf(d2, y.x, bv.x), fmaf(d2, y.y, bv.y),
                                   fmaf(d2, y.z, bv.z), fmaf(d2, y.w, bv.w));
            *(float4*)&Oini[(long long)gr * M + c0] = o;
        }
    }
}

// ---------------- edge scatter: out[dst] += w[e] * hin[src], vectorized ----------------
template <int M>
__global__ void __launch_bounds__(256)
k_scatter(const int* __restrict__ src, const int* __restrict__ dst,
          const float* __restrict__ hin, float* __restrict__ hout) {
    constexpr int TPE = M / 4;                     // threads per edge
    int gid = blockIdx.x * blockDim.x + threadIdx.x;
    int e = gid / TPE;
    if (e >= EPP) return;
    int c = (gid % TPE) * 4;
    int s = src[e], d = dst[e];
    float w = g_w[e];
    float4 h = *(const float4*)&hin[s * M + c];
    red_add_v4(&hout[d * M + c], w * h.x, w * h.y, w * h.z, w * h.w);
}

// ---------------- drug aggregation (fused count) ----------------
__global__ void __launch_bounds__(256)
k_drug_agg(const int* __restrict__ pds, const int* __restrict__ pdd,
           const float* __restrict__ h) {
    int gid = blockIdx.x * blockDim.x + threadIdx.x;
    int e = gid / (D2 / 4);
    if (e >= EPD) return;
    int c = (gid % (D2 / 4)) * 4;
    int s = pds[e], d = pdd[e];
    float4 hv = *(const float4*)&h[s * D2 + c];
    red_add_v4(&g_agg[d * D2 + c], hv.x, hv.y, hv.z, hv.w);
    if (c == 0) atomicAdd(&g_cnt[d], 1.0f);
}

// ---------------- final drug GEMM: out = mean @ Wl + bl + x_drug @ Wr ----------------
__global__ void __launch_bounds__(256)
k_drug_out(const float* __restrict__ xd, const float* __restrict__ Wl,
           const float* __restrict__ bl, const float* __restrict__ Wr,
           float* __restrict__ out) {
    __shared__ float Wls[D2 * OUTD];    // 2048
    __shared__ float Wrs[INP * OUTD];   // 8192
    __shared__ float bls[OUTD];
    __shared__ float Ms[4 * D2];
    __shared__ float Xs[4 * INP];
    const int tid = threadIdx.x;
    for (int i = tid; i < D2 * OUTD; i += 256) Wls[i] = Wl[i];
    for (int i = tid; i < INP * OUTD; i += 256) Wrs[i] = Wr[i];
    if (tid < OUTD) bls[tid] = bl[tid];
    const int row0 = blockIdx.x * 4;  // 5000 % 4 == 0
    for (int i = tid; i < 4 * D2; i += 256) {
        int r = row0 + i / D2;
        float cnt = fmaxf(g_cnt[r], 1.0f);
        Ms[i] = g_agg[r * D2 + (i % D2)] / cnt;
    }
    for (int i = tid; i < 4 * INP; i += 256)
        Xs[i] = xd[(row0 + i / INP) * INP + (i % INP)];
    __syncthreads();
    const int c = tid % OUTD;
    const int r = tid / OUTD;
    float acc = bls[c];
#pragma unroll
    for (int k = 0; k < D2; k++) acc = fmaf(Ms[r * D2 + k], Wls[k * OUTD + c], acc);
#pragma unroll 8
    for (int k = 0; k < INP; k++) acc = fmaf(Xs[r * INP + k], Wrs[k * OUTD + c], acc);
    out[(row0 + r) * OUTD + c] = acc;
}

// ---------------- host ----------------
extern "C" void kernel_launch(void* const* d_in, const int* in_sizes, int n_in,
                              void* d_out, int out_size) {
    const float *x_prot = 0, *x_drug = 0, *W1 = 0, *b1 = 0, *W2 = 0, *b2 = 0;
    const float *Wl = 0, *bl = 0, *Wr = 0;
    const int *pp = 0, *pds = 0, *pdd = 0;
    int n200k = 0, n8192 = 0, n64 = 0, n2048 = 0;
    for (int i = 0; i < n_in; i++) {
        int s = in_sizes[i];
        void* p = d_in[i];
        if (s == NP * INP)        x_prot = (const float*)p;
        else if (s == ND * INP)   x_drug = (const float*)p;
        else if (s == 2 * EPP)    pp = (const int*)p;
        else if (s == EPD) {      if (n200k++ == 0) pds = (const int*)p; else pdd = (const int*)p; }
        else if (s == INP * D1) { if (n8192++ == 0) W1 = (const float*)p; else Wr = (const float*)p; }
        else if (s == D1) {       if (n64++   == 0) b1 = (const float*)p; else bl = (const float*)p; }
        else if (s == D1 * D2) {  if (n2048++ == 0) W2 = (const float*)p; else Wl = (const float*)p; }
        else if (s == D2)         b2 = (const float*)p;
    }
    const int* pp_src = pp;
    const int* pp_dst = pp + EPP;
    float* h_out = (float*)d_out;                  // [NP, D2]
    float* drug_out = h_out + (long long)NP * D2;  // [ND, OUTD]

    float* g_h1_p; cudaGetSymbolAddress((void**)&g_h1_p, g_h1);
    float* g_o1_p; cudaGetSymbolAddress((void**)&g_o1_p, g_o1);
    float* g_h2_p; cudaGetSymbolAddress((void**)&g_h2_p, g_h2);

    // degrees + dinv + edge weights
    k_zero<<<256, 256>>>();
    k_degree<<<(EPP + 255) / 256, 256>>>(pp_dst);
    k_dinv<<<(NP + 255) / 256, 256>>>();
    k_edgew<<<(EPP + 255) / 256, 256>>>(pp_src, pp_dst);

    // layer 1: gemm (+fused self-loop/bias) -> scatter
    k_gemm<INP, D1, 32, false><<<(NP + 63) / 64, 256>>>(x_prot, W1, b1, g_h1_p, g_o1_p, NP);
    k_scatter<D1><<<(EPP * (D1 / 4) + 255) / 256, 256>>>(pp_src, pp_dst, g_h1_p, g_o1_p);

    // layer 2: relu fused into gemm load; init straight into d_out
    k_gemm<D1, D2, 64, true><<<(NP + 127) / 128, 256>>>(g_o1_p, W2, b2, g_h2_p, h_out, NP);
    k_scatter<D2><<<(EPP * (D2 / 4) + 255) / 256, 256>>>(pp_src, pp_dst, g_h2_p, h_out);

    // bipartite mean-SAGE
    k_drug_agg<<<(EPD * (D2 / 4) + 255) / 256, 256>>>(pds, pdd, h_out);
    k_drug_out<<<ND / 4, 256>>>(x_drug, Wl, bl, Wr, drug_out);

    (void)out_size;
}